// round 1
// baseline (speedup 1.0000x reference)
#include <cuda_runtime.h>
#include <math.h>

#define T      4096
#define DIM    1024
#define E      8
#define HDIM   2048
#define NSLOT  (T * 2)
#define EPS    1e-5f

// ---------------- device scratch (static, allocation-free) ----------------
__device__ float g_h[(size_t)NSLOT * HDIM];   // 64 MB: expert hidden activations
__device__ float g_y[(size_t)NSLOT * DIM];    // 32 MB: per-slot expert outputs (gate-scaled)
__device__ int   g_cnt[E];
__device__ int   g_cur[E];
__device__ int   g_off[E + 1];
__device__ int   g_topi[NSLOT];
__device__ float g_topw[NSLOT];
__device__ int   g_slot_token[NSLOT];
__device__ int   g_slot_e[NSLOT];
__device__ float g_slot_w[NSLOT];
__device__ int   g_tok_slot[NSLOT];

// ---------------- init ----------------
__global__ void init_kernel() {
    int t = threadIdx.x;
    if (t < E) { g_cnt[t] = 0; g_cur[t] = 0; }
}

// ---------------- gating: one warp per token ----------------
__global__ void gate_kernel(const float* __restrict__ x, const float* __restrict__ gw) {
    int warp = (blockIdx.x * blockDim.x + threadIdx.x) >> 5;
    int lane = threadIdx.x & 31;
    if (warp >= T) return;
    const float* xr = x + (size_t)warp * DIM;
    float acc[E];
#pragma unroll
    for (int e = 0; e < E; e++) acc[e] = 0.f;
    for (int d = lane; d < DIM; d += 32) {
        float xv = xr[d];
        const float* g = gw + d * E;
#pragma unroll
        for (int e = 0; e < E; e++) acc[e] += xv * g[e];
    }
#pragma unroll
    for (int e = 0; e < E; e++)
#pragma unroll
        for (int o = 16; o; o >>= 1) acc[e] += __shfl_xor_sync(0xffffffffu, acc[e], o);
    if (lane == 0) {
        int i1 = 0; float l1 = acc[0];
#pragma unroll
        for (int e = 1; e < E; e++) if (acc[e] > l1) { l1 = acc[e]; i1 = e; }
        int i2 = -1; float l2 = -INFINITY;
#pragma unroll
        for (int e = 0; e < E; e++) if (e != i1 && acc[e] > l2) { l2 = acc[e]; i2 = e; }
        // normalized top-2 softmax weights: denominators cancel exactly
        float w1 = 1.f / (1.f + __expf(l2 - l1) * 0.f + expf(l2 - l1) * 0.f + expf(l2 - l1));
        // (use precise expf only)
        w1 = 1.f / (1.f + expf(l2 - l1));
        g_topi[2 * warp]     = i1;  g_topi[2 * warp + 1] = i2;
        g_topw[2 * warp]     = w1;  g_topw[2 * warp + 1] = 1.f - w1;
        atomicAdd(&g_cnt[i1], 1);
        atomicAdd(&g_cnt[i2], 1);
    }
}

// ---------------- scan ----------------
__global__ void scan_kernel() {
    if (threadIdx.x == 0) {
        int acc = 0;
#pragma unroll
        for (int e = 0; e < E; e++) { g_off[e] = acc; acc += g_cnt[e]; }
        g_off[E] = acc;
    }
}

// ---------------- scatter ----------------
__global__ void scatter_kernel() {
    int t = blockIdx.x * blockDim.x + threadIdx.x;
    if (t >= T) return;
#pragma unroll
    for (int k = 0; k < 2; k++) {
        int e = g_topi[2 * t + k];
        int p = g_off[e] + atomicAdd(&g_cur[e], 1);
        g_slot_token[p] = t;
        g_slot_e[p]     = e;
        g_slot_w[p]     = g_topw[2 * t + k];
        g_tok_slot[2 * t + k] = p;
    }
}

// ---------------- grouped GEMM: 128x128x16 tile, 256 thr, 8x8 microtile ----
// MODE 0: A = gather(x) rows via slot_token; out = A@W + bias  -> g_h
// MODE 1: A = g_h rows (contiguous);        out = (A@W + bias)*slot_w -> g_y
template <int Ndim, int Kdim, int MODE>
__global__ __launch_bounds__(256) void moe_gemm(
    const float* __restrict__ Asrc, const float* __restrict__ W,
    const float* __restrict__ bias, float* __restrict__ out)
{
    const int e    = blockIdx.z;
    const int base = g_off[e];
    const int cnt  = g_off[e + 1] - base;
    const int row0 = blockIdx.y * 128;
    if (row0 >= cnt) return;
    const int n0 = blockIdx.x * 128;

    __shared__ float As[16][128];
    __shared__ float Bs[16][128];

    const int tid = threadIdx.x;
    const int ty = tid >> 4, tx = tid & 15;

    // A-tile load mapping: 512 float4 per tile, 2 per thread
    const int ar0 = tid >> 2;                 // rows 0..63
    const int ar1 = ar0 + 64;                 // rows 64..127
    const int akq = (tid & 3) * 4;            // k offset 0/4/8/12

    const float* arow0p;
    const float* arow1p;
    {
        int r0 = min(row0 + ar0, cnt - 1);
        int r1 = min(row0 + ar1, cnt - 1);
        if (MODE == 0) {
            arow0p = Asrc + (size_t)g_slot_token[base + r0] * Kdim;
            arow1p = Asrc + (size_t)g_slot_token[base + r1] * Kdim;
        } else {
            arow0p = Asrc + (size_t)(base + r0) * Kdim;
            arow1p = Asrc + (size_t)(base + r1) * Kdim;
        }
    }
    const float* Wp = W + (size_t)e * Kdim * Ndim + n0;
    const int bk  = tid >> 5;                 // B k-row 0..7
    const int bnq = (tid & 31) * 4;           // B n offset

    float c[8][8];
#pragma unroll
    for (int i = 0; i < 8; i++)
#pragma unroll
        for (int j = 0; j < 8; j++) c[i][j] = 0.f;

    for (int k0 = 0; k0 < Kdim; k0 += 16) {
        float4 a0 = *(const float4*)(arow0p + k0 + akq);
        float4 a1 = *(const float4*)(arow1p + k0 + akq);
        float4 b0 = *(const float4*)(Wp + (size_t)(k0 + bk) * Ndim + bnq);
        float4 b1 = *(const float4*)(Wp + (size_t)(k0 + 8 + bk) * Ndim + bnq);
        __syncthreads();
        As[akq + 0][ar0] = a0.x; As[akq + 1][ar0] = a0.y;
        As[akq + 2][ar0] = a0.z; As[akq + 3][ar0] = a0.w;
        As[akq + 0][ar1] = a1.x; As[akq + 1][ar1] = a1.y;
        As[akq + 2][ar1] = a1.z; As[akq + 3][ar1] = a1.w;
        *(float4*)&Bs[bk][bnq]     = b0;
        *(float4*)&Bs[bk + 8][bnq] = b1;
        __syncthreads();
#pragma unroll
        for (int k = 0; k < 16; k++) {
            float ra[8], rb[8];
            *(float4*)(ra)     = *(const float4*)&As[k][ty * 8];
            *(float4*)(ra + 4) = *(const float4*)&As[k][ty * 8 + 4];
            *(float4*)(rb)     = *(const float4*)&Bs[k][tx * 8];
            *(float4*)(rb + 4) = *(const float4*)&Bs[k][tx * 8 + 4];
#pragma unroll
            for (int i = 0; i < 8; i++)
#pragma unroll
                for (int j = 0; j < 8; j++) c[i][j] += ra[i] * rb[j];
        }
    }

    const float* bi = bias + (size_t)e * Ndim + n0 + tx * 8;
#pragma unroll
    for (int i = 0; i < 8; i++) {
        int r = row0 + ty * 8 + i;
        if (r >= cnt) break;
        size_t slot = (size_t)(base + r);
        float* orow = out + slot * Ndim + n0 + tx * 8;
        if (MODE == 0) {
#pragma unroll
            for (int j = 0; j < 8; j++) orow[j] = c[i][j] + bi[j];
        } else {
            float wgt = g_slot_w[slot];
#pragma unroll
            for (int j = 0; j < 8; j++) orow[j] = (c[i][j] + bi[j]) * wgt;
        }
    }
}

// ---------------- block reduction helper (sum, sumsq) ----------------
__device__ __forceinline__ float2 block_reduce2(float a, float b) {
#pragma unroll
    for (int o = 16; o; o >>= 1) {
        a += __shfl_xor_sync(0xffffffffu, a, o);
        b += __shfl_xor_sync(0xffffffffu, b, o);
    }
    __shared__ float2 sm[8];
    int w = threadIdx.x >> 5, l = threadIdx.x & 31;
    if (l == 0) sm[w] = make_float2(a, b);
    __syncthreads();
    if (w == 0) {
        float2 v = (l < 8) ? sm[l] : make_float2(0.f, 0.f);
#pragma unroll
        for (int o = 4; o; o >>= 1) {
            v.x += __shfl_xor_sync(0xffffffffu, v.x, o);
            v.y += __shfl_xor_sync(0xffffffffu, v.y, o);
        }
        if (l == 0) sm[0] = v;
    }
    __syncthreads();
    return sm[0];
}

// ---------------- LN1 + exact GELU over g_h rows ----------------
__global__ __launch_bounds__(256) void ln_gelu_kernel(
    const float* __restrict__ ln1_g, const float* __restrict__ ln1_b)
{
    int s = blockIdx.x;                 // 8192 slot rows
    int e = g_slot_e[s];
    float* row = g_h + (size_t)s * HDIM;
    int t = threadIdx.x;

    float4 v0 = ((float4*)row)[t];
    float4 v1 = ((float4*)row)[t + 256];
    float sum = v0.x + v0.y + v0.z + v0.w + v1.x + v1.y + v1.z + v1.w;
    float sq  = v0.x * v0.x + v0.y * v0.y + v0.z * v0.z + v0.w * v0.w
              + v1.x * v1.x + v1.y * v1.y + v1.z * v1.z + v1.w * v1.w;
    float2 r = block_reduce2(sum, sq);
    float mean = r.x * (1.f / HDIM);
    float var  = r.y * (1.f / HDIM) - mean * mean;
    float rstd = rsqrtf(var + EPS);

    const float4 gg0 = ((const float4*)(ln1_g + (size_t)e * HDIM))[t];
    const float4 gg1 = ((const float4*)(ln1_g + (size_t)e * HDIM))[t + 256];
    const float4 bb0 = ((const float4*)(ln1_b + (size_t)e * HDIM))[t];
    const float4 bb1 = ((const float4*)(ln1_b + (size_t)e * HDIM))[t + 256];

    float va[8] = {v0.x, v0.y, v0.z, v0.w, v1.x, v1.y, v1.z, v1.w};
    float ga[8] = {gg0.x, gg0.y, gg0.z, gg0.w, gg1.x, gg1.y, gg1.z, gg1.w};
    float ba[8] = {bb0.x, bb0.y, bb0.z, bb0.w, bb1.x, bb1.y, bb1.z, bb1.w};
#pragma unroll
    for (int i = 0; i < 8; i++) {
        float u = (va[i] - mean) * rstd * ga[i] + ba[i];
        va[i] = 0.5f * u * (1.f + erff(u * 0.70710678118654752f));
    }
    ((float4*)row)[t]       = make_float4(va[0], va[1], va[2], va[3]);
    ((float4*)row)[t + 256] = make_float4(va[4], va[5], va[6], va[7]);
}

// ---------------- combine: out = LN(x + y_slot0 + y_slot1) ----------------
__global__ __launch_bounds__(256) void combine_kernel(
    const float* __restrict__ x, const float* __restrict__ ln_g,
    const float* __restrict__ ln_b, float* __restrict__ outp)
{
    int tkn = blockIdx.x;               // 4096 tokens
    int s0 = g_tok_slot[2 * tkn], s1 = g_tok_slot[2 * tkn + 1];
    int t = threadIdx.x;                // 4 floats each (1024/256)

    float4 xv = ((const float4*)(x + (size_t)tkn * DIM))[t];
    float4 y0 = ((const float4*)(g_y + (size_t)s0 * DIM))[t];
    float4 y1 = ((const float4*)(g_y + (size_t)s1 * DIM))[t];
    float4 v = make_float4(xv.x + y0.x + y1.x, xv.y + y0.y + y1.y,
                           xv.z + y0.z + y1.z, xv.w + y0.w + y1.w);
    float sum = v.x + v.y + v.z + v.w;
    float sq  = v.x * v.x + v.y * v.y + v.z * v.z + v.w * v.w;
    float2 r = block_reduce2(sum, sq);
    float mean = r.x * (1.f / DIM);
    float var  = r.y * (1.f / DIM) - mean * mean;
    float rstd = rsqrtf(var + EPS);

    float4 gg = ((const float4*)ln_g)[t];
    float4 bb = ((const float4*)ln_b)[t];
    float4 o = make_float4((v.x - mean) * rstd * gg.x + bb.x,
                           (v.y - mean) * rstd * gg.y + bb.y,
                           (v.z - mean) * rstd * gg.z + bb.z,
                           (v.w - mean) * rstd * gg.w + bb.w);
    ((float4*)(outp + (size_t)tkn * DIM))[t] = o;
}

// ---------------- launch ----------------
extern "C" void kernel_launch(void* const* d_in, const int* in_sizes, int n_in,
                              void* d_out, int out_size) {
    const float* x      = (const float*)d_in[0];
    const float* gate_w = (const float*)d_in[1];
    const float* w1     = (const float*)d_in[2];
    const float* b1     = (const float*)d_in[3];
    const float* ln1_g  = (const float*)d_in[4];
    const float* ln1_b  = (const float*)d_in[5];
    const float* w2     = (const float*)d_in[6];
    const float* b2     = (const float*)d_in[7];
    const float* ln_g   = (const float*)d_in[8];
    const float* ln_b   = (const float*)d_in[9];
    float* outp = (float*)d_out;

    init_kernel<<<1, 32>>>();
    gate_kernel<<<T / 8, 256>>>(x, gate_w);          // 8 warps/block
    scan_kernel<<<1, 32>>>();
    scatter_kernel<<<T / 256, 256>>>();

    // GEMM1: [cnt_e,1024] @ [1024,2048] -> g_h
    {
        float* hptr; cudaGetSymbolAddress((void**)&hptr, g_h);
        dim3 grid(HDIM / 128, T / 128, E);            // worst-case rows per expert
        moe_gemm<HDIM, DIM, 0><<<grid, 256>>>(x, w1, b1, hptr);
        ln_gelu_kernel<<<NSLOT, 256>>>(ln1_g, ln1_b);
        // GEMM2: [cnt_e,2048] @ [2048,1024] -> g_y (gate-scaled)
        float* yptr; cudaGetSymbolAddress((void**)&yptr, g_y);
        dim3 grid2(DIM / 128, T / 128, E);
        moe_gemm<DIM, HDIM, 1><<<grid2, 256>>>(hptr, w2, b2, yptr);
    }
    combine_kernel<<<T, 256>>>(x, ln_g, ln_b, outp);
}

// round 3
// speedup vs baseline: 2.3553x; 2.3553x over previous
#include <cuda_runtime.h>
#include <cuda_bf16.h>
#include <math.h>
#include <stdint.h>

#define T      4096
#define DIM    1024
#define E      8
#define HDIM   2048
#define NSLOT  (T * 2)
#define EPS    1e-5f

// ---------------- device scratch (static, allocation-free) ----------------
__device__ float g_h[(size_t)NSLOT * HDIM];
__device__ float g_y[(size_t)NSLOT * DIM];
__device__ __nv_bfloat16 g_xh[(size_t)T * DIM];
__device__ __nv_bfloat16 g_xl[(size_t)T * DIM];
__device__ __nv_bfloat16 g_hbh[(size_t)NSLOT * HDIM];
__device__ __nv_bfloat16 g_hbl[(size_t)NSLOT * HDIM];
__device__ __nv_bfloat16 g_w1h[(size_t)E * DIM * HDIM];   // [E][K=1024][N=2048]
__device__ __nv_bfloat16 g_w1l[(size_t)E * DIM * HDIM];
__device__ __nv_bfloat16 g_w2h[(size_t)E * HDIM * DIM];   // [E][K=2048][N=1024]
__device__ __nv_bfloat16 g_w2l[(size_t)E * HDIM * DIM];
__device__ int   g_cnt[E];
__device__ int   g_cur[E];
__device__ int   g_off[E + 1];
__device__ int   g_topi[NSLOT];
__device__ float g_topw[NSLOT];
__device__ int   g_slot_token[NSLOT];
__device__ int   g_slot_e[NSLOT];
__device__ float g_slot_w[NSLOT];
__device__ int   g_tok_slot[NSLOT];

// ---------------- PTX helpers ----------------
__device__ __forceinline__ uint32_t s2u(const void* p) {
    uint32_t a;
    asm("{ .reg .u64 t; cvta.to.shared.u64 t, %1; cvt.u32.u64 %0, t; }" : "=r"(a) : "l"(p));
    return a;
}

#define CP_ASYNC(sa, ga) \
    asm volatile("cp.async.cg.shared.global [%0], [%1], 16;" :: "r"(sa), "l"(ga))
#define CP_COMMIT() asm volatile("cp.async.commit_group;" ::: "memory")
#define CP_WAIT1()  asm volatile("cp.async.wait_group 1;" ::: "memory")

#define LDSM4(r, addr) \
    asm volatile("ldmatrix.sync.aligned.m8n8.x4.shared.b16 {%0,%1,%2,%3}, [%4];" \
        : "=r"((r)[0]), "=r"((r)[1]), "=r"((r)[2]), "=r"((r)[3]) : "r"(addr))
#define LDSM4T(r, addr) \
    asm volatile("ldmatrix.sync.aligned.m8n8.x4.trans.shared.b16 {%0,%1,%2,%3}, [%4];" \
        : "=r"((r)[0]), "=r"((r)[1]), "=r"((r)[2]), "=r"((r)[3]) : "r"(addr))

#define MMA(acc, a, b) \
    asm volatile("mma.sync.aligned.m16n8k16.row.col.f32.bf16.bf16.f32 " \
        "{%0,%1,%2,%3}, {%4,%5,%6,%7}, {%8,%9}, {%0,%1,%2,%3};" \
        : "+f"((acc)[0]), "+f"((acc)[1]), "+f"((acc)[2]), "+f"((acc)[3]) \
        : "r"((a)[0]), "r"((a)[1]), "r"((a)[2]), "r"((a)[3]), "r"((b)[0]), "r"((b)[1]))

// ---------------- small routing kernels ----------------
__global__ void init_kernel() {
    int t = threadIdx.x;
    if (t < E) { g_cnt[t] = 0; g_cur[t] = 0; }
}

__global__ void gate_kernel(const float* __restrict__ x, const float* __restrict__ gw) {
    int warp = (blockIdx.x * blockDim.x + threadIdx.x) >> 5;
    int lane = threadIdx.x & 31;
    if (warp >= T) return;
    const float* xr = x + (size_t)warp * DIM;
    float acc[E];
#pragma unroll
    for (int e = 0; e < E; e++) acc[e] = 0.f;
    for (int d = lane; d < DIM; d += 32) {
        float xv = xr[d];
        const float* g = gw + d * E;
#pragma unroll
        for (int e = 0; e < E; e++) acc[e] += xv * g[e];
    }
#pragma unroll
    for (int e = 0; e < E; e++)
#pragma unroll
        for (int o = 16; o; o >>= 1) acc[e] += __shfl_xor_sync(0xffffffffu, acc[e], o);
    if (lane == 0) {
        int i1 = 0; float l1 = acc[0];
#pragma unroll
        for (int e = 1; e < E; e++) if (acc[e] > l1) { l1 = acc[e]; i1 = e; }
        int i2 = -1; float l2 = -INFINITY;
#pragma unroll
        for (int e = 0; e < E; e++) if (e != i1 && acc[e] > l2) { l2 = acc[e]; i2 = e; }
        float w1 = 1.f / (1.f + expf(l2 - l1));   // exact normalized top-2 softmax
        g_topi[2 * warp] = i1;  g_topi[2 * warp + 1] = i2;
        g_topw[2 * warp] = w1;  g_topw[2 * warp + 1] = 1.f - w1;
        atomicAdd(&g_cnt[i1], 1);
        atomicAdd(&g_cnt[i2], 1);
    }
}

__global__ void scan_kernel() {
    if (threadIdx.x == 0) {
        int acc = 0;
#pragma unroll
        for (int e = 0; e < E; e++) { g_off[e] = acc; acc += g_cnt[e]; }
        g_off[E] = acc;
    }
}

__global__ void scatter_kernel() {
    int t = blockIdx.x * blockDim.x + threadIdx.x;
    if (t >= T) return;
#pragma unroll
    for (int k = 0; k < 2; k++) {
        int e = g_topi[2 * t + k];
        int p = g_off[e] + atomicAdd(&g_cur[e], 1);
        g_slot_token[p] = t;
        g_slot_e[p]     = e;
        g_slot_w[p]     = g_topw[2 * t + k];
        g_tok_slot[2 * t + k] = p;
    }
}

// ---------------- conversions: fp32 -> bf16 hi/lo (same layout) ----------------
__global__ void convert_x_kernel(const float* __restrict__ x) {
    int i = blockIdx.x * blockDim.x + threadIdx.x;
    float4 v = ((const float4*)x)[i];
    float va[4] = {v.x, v.y, v.z, v.w};
    __nv_bfloat16 h[4], l[4];
#pragma unroll
    for (int j = 0; j < 4; j++) {
        h[j] = __float2bfloat16(va[j]);
        l[j] = __float2bfloat16(va[j] - __bfloat162float(h[j]));
    }
    __nv_bfloat162* ph = (__nv_bfloat162*)g_xh;
    __nv_bfloat162* pl = (__nv_bfloat162*)g_xl;
    __nv_bfloat162 a, b;
    a.x = h[0]; a.y = h[1]; b.x = h[2]; b.y = h[3];
    ph[2 * i] = a; ph[2 * i + 1] = b;
    a.x = l[0]; a.y = l[1]; b.x = l[2]; b.y = l[3];
    pl[2 * i] = a; pl[2 * i + 1] = b;
}

template <int WSEL>   // 0 -> w1, 1 -> w2
__global__ void convert_w_kernel(const float* __restrict__ W) {
    __nv_bfloat16* __restrict__ Wh = (WSEL == 0) ? g_w1h : g_w2h;
    __nv_bfloat16* __restrict__ Wl = (WSEL == 0) ? g_w1l : g_w2l;
    size_t i = (size_t)blockIdx.x * blockDim.x + threadIdx.x;
    float4 v = ((const float4*)W)[i];
    float va[4] = {v.x, v.y, v.z, v.w};
    __nv_bfloat16 h[4], l[4];
#pragma unroll
    for (int j = 0; j < 4; j++) {
        h[j] = __float2bfloat16(va[j]);
        l[j] = __float2bfloat16(va[j] - __bfloat162float(h[j]));
    }
    __nv_bfloat162* ph = (__nv_bfloat162*)Wh;
    __nv_bfloat162* pl = (__nv_bfloat162*)Wl;
    __nv_bfloat162 a, b;
    a.x = h[0]; a.y = h[1]; b.x = h[2]; b.y = h[3];
    ph[2 * i] = a; ph[2 * i + 1] = b;
    a.x = l[0]; a.y = l[1]; b.x = l[2]; b.y = l[3];
    pl[2 * i] = a; pl[2 * i + 1] = b;
}

// ---------------- mma.sync grouped GEMM ----------------
// Block tile 128(M) x 128(N), K-stage 32, 8 warps (2x4), warp tile 64x32.
// bf16 hi/lo split: acc += Ah*Bh + Ah*Bl + Al*Bh  (fp32 accum, ~1e-5 rel err)
// A smem: [128][32] bf16, row stride 80B (conflict-free ldmatrix)
// B smem: [32][128] bf16, row stride 272B (conflict-free ldmatrix.trans)
#define A_STRIDE 80
#define B_STRIDE 272
#define AH_OFF   0
#define AL_OFF   (128 * A_STRIDE)            // 10240
#define BH_OFF   (2 * 128 * A_STRIDE)        // 20480
#define BL_OFF   (BH_OFF + 32 * B_STRIDE)    // 29184
#define STAGE_SZ (BL_OFF + 32 * B_STRIDE)    // 37888
#define NSTAGE   3
#define MM_SMEM  (1024 + NSTAGE * STAGE_SZ)  // 114688

template <int NT, int KD, int MODE>
__global__ void __launch_bounds__(256, 1) mma_gemm(const float* __restrict__ bias) {
    const int e    = blockIdx.z;
    const int base = g_off[e];
    const int cnt  = g_off[e + 1] - base;
    const int row0 = blockIdx.y * 128;
    if (row0 >= cnt) return;
    const int n0 = blockIdx.x * 128;

    extern __shared__ __align__(128) char smem[];
    const uint32_t sb = s2u(smem);
    int* rowidx = (int*)smem;
    const int tid = threadIdx.x, wid = tid >> 5, lane = tid & 31;

    const __nv_bfloat16* __restrict__ Ahi = (MODE == 0) ? g_xh  : g_hbh;
    const __nv_bfloat16* __restrict__ Alo = (MODE == 0) ? g_xl  : g_hbl;
    const __nv_bfloat16* __restrict__ bhp =
        ((MODE == 0) ? g_w1h : g_w2h) + (size_t)e * KD * NT + n0;
    const __nv_bfloat16* __restrict__ blp =
        ((MODE == 0) ? g_w1l : g_w2l) + (size_t)e * KD * NT + n0;
    float* __restrict__ out = (MODE == 0) ? g_h : g_y;

    if (tid < 128) {
        int r = row0 + tid; if (r > cnt - 1) r = cnt - 1;
        rowidx[tid] = (MODE == 0) ? g_slot_token[base + r] : (base + r);
    }
    __syncthreads();

    // per-thread cp.async coordinates
    const int ar = tid >> 2, ac = tid & 3;       // A: rows ar, ar+64; chunk ac
    const int br = tid >> 4, bc = tid & 15;      // B: rows br, br+16; chunk bc

    auto issue = [&](int c) {
        const int k0 = c * 32;
        const uint32_t s = sb + 1024 + (c % NSTAGE) * STAGE_SZ;
#pragma unroll
        for (int i = 0; i < 2; i++) {
            int row = ar + i * 64;
            size_t go = (size_t)rowidx[row] * KD + k0 + ac * 8;
            uint32_t so = s + row * A_STRIDE + ac * 16;
            CP_ASYNC(so + AH_OFF, Ahi + go);
            CP_ASYNC(so + AL_OFF, Alo + go);
        }
#pragma unroll
        for (int i = 0; i < 2; i++) {
            int row = br + i * 16;
            size_t go = (size_t)(k0 + row) * NT + bc * 8;
            uint32_t so = s + row * B_STRIDE + bc * 16;
            CP_ASYNC(so + BH_OFF, bhp + go);
            CP_ASYNC(so + BL_OFF, blp + go);
        }
        CP_COMMIT();
    };

    float acc[4][4][4];
#pragma unroll
    for (int i = 0; i < 4; i++)
#pragma unroll
        for (int j = 0; j < 4; j++)
#pragma unroll
            for (int q = 0; q < 4; q++) acc[i][j][q] = 0.f;

    const int warp_m = wid >> 2, warp_n = wid & 3;
    const int mat = lane >> 3, rin = lane & 7;
    // ldmatrix lane base addresses (relative to stage base)
    const uint32_t aOffBase = (uint32_t)((warp_m * 64 + rin + (mat & 1) * 8) * A_STRIDE
                                         + (mat >> 1) * 16);
    const uint32_t bOffBase = (uint32_t)(BH_OFF + ((mat & 1) * 8 + rin) * B_STRIDE
                                         + (warp_n * 32 + (mat >> 1) * 8) * 2);

    constexpr int NCH = KD / 32;
    issue(0);
    issue(1);

    for (int c = 0; c < NCH; c++) {
        CP_WAIT1();
        __syncthreads();
        const uint32_t s = sb + 1024 + (c % NSTAGE) * STAGE_SZ;
#pragma unroll
        for (int ks = 0; ks < 2; ks++) {
            uint32_t ah[4][4], al[4][4], bh[4][2], bl[4][2];
            uint32_t aAddr = s + aOffBase + ks * 32;
#pragma unroll
            for (int i = 0; i < 4; i++) LDSM4(ah[i], aAddr + i * 16 * A_STRIDE);
#pragma unroll
            for (int i = 0; i < 4; i++) LDSM4(al[i], aAddr + AL_OFF + i * 16 * A_STRIDE);
            uint32_t bAddr = s + bOffBase + ks * 16 * B_STRIDE;
            LDSM4T(&bh[0][0], bAddr);
            LDSM4T(&bh[2][0], bAddr + 32);
            LDSM4T(&bl[0][0], bAddr + (BL_OFF - BH_OFF));
            LDSM4T(&bl[2][0], bAddr + (BL_OFF - BH_OFF) + 32);
#pragma unroll
            for (int i = 0; i < 4; i++)
#pragma unroll
                for (int j = 0; j < 4; j++) MMA(acc[i][j], ah[i], bh[j]);
#pragma unroll
            for (int i = 0; i < 4; i++)
#pragma unroll
                for (int j = 0; j < 4; j++) MMA(acc[i][j], ah[i], bl[j]);
#pragma unroll
            for (int i = 0; i < 4; i++)
#pragma unroll
                for (int j = 0; j < 4; j++) MMA(acc[i][j], al[i], bh[j]);
        }
        if (c + 2 < NCH) issue(c + 2);
        else CP_COMMIT();
    }

    // epilogue
    const float* bp = bias + (size_t)e * NT;
#pragma unroll
    for (int i = 0; i < 4; i++) {
        int r1 = row0 + warp_m * 64 + i * 16 + (lane >> 2);
        int r2 = r1 + 8;
        bool v1 = r1 < cnt, v2 = r2 < cnt;
        float w1g = 1.f, w2g = 1.f;
        if (MODE == 1) {
            if (v1) w1g = g_slot_w[base + r1];
            if (v2) w2g = g_slot_w[base + r2];
        }
#pragma unroll
        for (int j = 0; j < 4; j++) {
            int col = n0 + warp_n * 32 + j * 8 + (lane & 3) * 2;
            float b0 = bp[col], b1 = bp[col + 1];
            if (v1) {
                float2 o = make_float2((acc[i][j][0] + b0) * w1g,
                                       (acc[i][j][1] + b1) * w1g);
                *(float2*)(out + (size_t)(base + r1) * NT + col) = o;
            }
            if (v2) {
                float2 o = make_float2((acc[i][j][2] + b0) * w2g,
                                       (acc[i][j][3] + b1) * w2g);
                *(float2*)(out + (size_t)(base + r2) * NT + col) = o;
            }
        }
    }
}

// ---------------- block reduction helper ----------------
__device__ __forceinline__ float2 block_reduce2(float a, float b) {
#pragma unroll
    for (int o = 16; o; o >>= 1) {
        a += __shfl_xor_sync(0xffffffffu, a, o);
        b += __shfl_xor_sync(0xffffffffu, b, o);
    }
    __shared__ float2 sm[8];
    int w = threadIdx.x >> 5, l = threadIdx.x & 31;
    if (l == 0) sm[w] = make_float2(a, b);
    __syncthreads();
    if (w == 0) {
        float2 v = (l < 8) ? sm[l] : make_float2(0.f, 0.f);
#pragma unroll
        for (int o = 4; o; o >>= 1) {
            v.x += __shfl_xor_sync(0xffffffffu, v.x, o);
            v.y += __shfl_xor_sync(0xffffffffu, v.y, o);
        }
        if (l == 0) sm[0] = v;
    }
    __syncthreads();
    return sm[0];
}

// ---------------- LN1 + exact GELU, emit bf16 hi/lo ----------------
__global__ __launch_bounds__(256) void ln_gelu_kernel(
    const float* __restrict__ ln1_g, const float* __restrict__ ln1_b) {
    int s = blockIdx.x;
    int e = g_slot_e[s];
    const float* row = g_h + (size_t)s * HDIM;
    int t = threadIdx.x;

    float4 v0 = ((const float4*)row)[t];
    float4 v1 = ((const float4*)row)[t + 256];
    float sum = v0.x + v0.y + v0.z + v0.w + v1.x + v1.y + v1.z + v1.w;
    float sq  = v0.x * v0.x + v0.y * v0.y + v0.z * v0.z + v0.w * v0.w
              + v1.x * v1.x + v1.y * v1.y + v1.z * v1.z + v1.w * v1.w;
    float2 r = block_reduce2(sum, sq);
    float mean = r.x * (1.f / HDIM);
    float var  = r.y * (1.f / HDIM) - mean * mean;
    float rstd = rsqrtf(var + EPS);

    const float4 gg0 = ((const float4*)(ln1_g + (size_t)e * HDIM))[t];
    const float4 gg1 = ((const float4*)(ln1_g + (size_t)e * HDIM))[t + 256];
    const float4 bb0 = ((const float4*)(ln1_b + (size_t)e * HDIM))[t];
    const float4 bb1 = ((const float4*)(ln1_b + (size_t)e * HDIM))[t + 256];

    float va[8] = {v0.x, v0.y, v0.z, v0.w, v1.x, v1.y, v1.z, v1.w};
    float ga[8] = {gg0.x, gg0.y, gg0.z, gg0.w, gg1.x, gg1.y, gg1.z, gg1.w};
    float ba[8] = {bb0.x, bb0.y, bb0.z, bb0.w, bb1.x, bb1.y, bb1.z, bb1.w};
    __nv_bfloat16 hv[8], lv[8];
#pragma unroll
    for (int i = 0; i < 8; i++) {
        float u = (va[i] - mean) * rstd * ga[i] + ba[i];
        float g = 0.5f * u * (1.f + erff(u * 0.70710678118654752f));
        hv[i] = __float2bfloat16(g);
        lv[i] = __float2bfloat16(g - __bfloat162float(hv[i]));
    }
    __nv_bfloat162* ph = (__nv_bfloat162*)(g_hbh + (size_t)s * HDIM);
    __nv_bfloat162* pl = (__nv_bfloat162*)(g_hbl + (size_t)s * HDIM);
    __nv_bfloat162 p;
    p.x = hv[0]; p.y = hv[1]; ph[2 * t] = p;
    p.x = hv[2]; p.y = hv[3]; ph[2 * t + 1] = p;
    p.x = hv[4]; p.y = hv[5]; ph[512 + 2 * t] = p;
    p.x = hv[6]; p.y = hv[7]; ph[512 + 2 * t + 1] = p;
    p.x = lv[0]; p.y = lv[1]; pl[2 * t] = p;
    p.x = lv[2]; p.y = lv[3]; pl[2 * t + 1] = p;
    p.x = lv[4]; p.y = lv[5]; pl[512 + 2 * t] = p;
    p.x = lv[6]; p.y = lv[7]; pl[512 + 2 * t + 1] = p;
}

// ---------------- combine: out = LN(x + y0 + y1) ----------------
__global__ __launch_bounds__(256) void combine_kernel(
    const float* __restrict__ x, const float* __restrict__ ln_g,
    const float* __restrict__ ln_b, float* __restrict__ outp) {
    int tkn = blockIdx.x;
    int s0 = g_tok_slot[2 * tkn], s1 = g_tok_slot[2 * tkn + 1];
    int t = threadIdx.x;

    float4 xv = ((const float4*)(x + (size_t)tkn * DIM))[t];
    float4 y0 = ((const float4*)(g_y + (size_t)s0 * DIM))[t];
    float4 y1 = ((const float4*)(g_y + (size_t)s1 * DIM))[t];
    float4 v = make_float4(xv.x + y0.x + y1.x, xv.y + y0.y + y1.y,
                           xv.z + y0.z + y1.z, xv.w + y0.w + y1.w);
    float sum = v.x + v.y + v.z + v.w;
    float sq  = v.x * v.x + v.y * v.y + v.z * v.z + v.w * v.w;
    float2 r = block_reduce2(sum, sq);
    float mean = r.x * (1.f / DIM);
    float var  = r.y * (1.f / DIM) - mean * mean;
    float rstd = rsqrtf(var + EPS);

    float4 gg = ((const float4*)ln_g)[t];
    float4 bb = ((const float4*)ln_b)[t];
    float4 o = make_float4((v.x - mean) * rstd * gg.x + bb.x,
                           (v.y - mean) * rstd * gg.y + bb.y,
                           (v.z - mean) * rstd * gg.z + bb.z,
                           (v.w - mean) * rstd * gg.w + bb.w);
    ((float4*)(outp + (size_t)tkn * DIM))[t] = o;
}

// ---------------- launch ----------------
extern "C" void kernel_launch(void* const* d_in, const int* in_sizes, int n_in,
                              void* d_out, int out_size) {
    const float* x      = (const float*)d_in[0];
    const float* gate_w = (const float*)d_in[1];
    const float* w1     = (const float*)d_in[2];
    const float* b1     = (const float*)d_in[3];
    const float* ln1_g  = (const float*)d_in[4];
    const float* ln1_b  = (const float*)d_in[5];
    const float* w2     = (const float*)d_in[6];
    const float* b2     = (const float*)d_in[7];
    const float* ln_g   = (const float*)d_in[8];
    const float* ln_b   = (const float*)d_in[9];
    float* outp = (float*)d_out;

    cudaFuncSetAttribute(mma_gemm<HDIM, DIM, 0>,
                         cudaFuncAttributeMaxDynamicSharedMemorySize, MM_SMEM);
    cudaFuncSetAttribute(mma_gemm<DIM, HDIM, 1>,
                         cudaFuncAttributeMaxDynamicSharedMemorySize, MM_SMEM);

    init_kernel<<<1, 32>>>();
    gate_kernel<<<T / 8, 256>>>(x, gate_w);
    scan_kernel<<<1, 32>>>();
    scatter_kernel<<<T / 256, 256>>>();

    convert_x_kernel<<<(T * DIM / 4) / 256, 256>>>(x);
    convert_w_kernel<0><<<(int)(((size_t)E * DIM * HDIM / 4) / 256), 256>>>(w1);
    convert_w_kernel<1><<<(int)(((size_t)E * HDIM * DIM / 4) / 256), 256>>>(w2);

    // GEMM1: gathered x @ w1 + b1 -> g_h (fp32)
    mma_gemm<HDIM, DIM, 0><<<dim3(HDIM / 128, T / 128, E), 256, MM_SMEM>>>(b1);
    ln_gelu_kernel<<<NSLOT, 256>>>(ln1_g, ln1_b);
    // GEMM2: act @ w2 + b2, gate-scaled -> g_y
    mma_gemm<DIM, HDIM, 1><<<dim3(DIM / 128, T / 128, E), 256, MM_SMEM>>>(b2);
    combine_kernel<<<T, 256>>>(x, ln_g, ln_b, outp);
}

// round 4
// speedup vs baseline: 2.5426x; 1.0795x over previous
#include <cuda_runtime.h>
#include <cuda_bf16.h>
#include <math.h>
#include <stdint.h>

#define T      4096
#define DIM    1024
#define E      8
#define HDIM   2048
#define NSLOT  (T * 2)
#define EPS    1e-5f

// ---------------- device scratch (static, allocation-free) ----------------
__device__ float g_h[(size_t)NSLOT * HDIM];
__device__ float g_y[(size_t)NSLOT * DIM];
__device__ __nv_bfloat16 g_xh[(size_t)T * DIM];
__device__ __nv_bfloat16 g_xl[(size_t)T * DIM];
__device__ __nv_bfloat16 g_hbh[(size_t)NSLOT * HDIM];
__device__ __nv_bfloat16 g_hbl[(size_t)NSLOT * HDIM];
__device__ __nv_bfloat16 g_w1h[(size_t)E * DIM * HDIM];   // [E][K=1024][N=2048]
__device__ __nv_bfloat16 g_w1l[(size_t)E * DIM * HDIM];
__device__ __nv_bfloat16 g_w2h[(size_t)E * HDIM * DIM];   // [E][K=2048][N=1024]
__device__ __nv_bfloat16 g_w2l[(size_t)E * HDIM * DIM];
__device__ int   g_cnt[E];
__device__ int   g_cur[E];
__device__ int   g_off[E + 1];
__device__ int   g_topi[NSLOT];
__device__ float g_topw[NSLOT];
__device__ int   g_slot_token[NSLOT];
__device__ int   g_slot_e[NSLOT];
__device__ float g_slot_w[NSLOT];
__device__ int   g_tok_slot[NSLOT];

// ---------------- PTX helpers ----------------
__device__ __forceinline__ uint32_t s2u(const void* p) {
    uint32_t a;
    asm("{ .reg .u64 t; cvta.to.shared.u64 t, %1; cvt.u32.u64 %0, t; }" : "=r"(a) : "l"(p));
    return a;
}

#define CP_ASYNC(sa, ga) \
    asm volatile("cp.async.cg.shared.global [%0], [%1], 16;" :: "r"(sa), "l"(ga))
#define CP_COMMIT() asm volatile("cp.async.commit_group;" ::: "memory")
#define CP_WAIT2()  asm volatile("cp.async.wait_group 2;" ::: "memory")

#define LDSM4(r, addr) \
    asm volatile("ldmatrix.sync.aligned.m8n8.x4.shared.b16 {%0,%1,%2,%3}, [%4];" \
        : "=r"((r)[0]), "=r"((r)[1]), "=r"((r)[2]), "=r"((r)[3]) : "r"(addr))
#define LDSM4T(r, addr) \
    asm volatile("ldmatrix.sync.aligned.m8n8.x4.trans.shared.b16 {%0,%1,%2,%3}, [%4];" \
        : "=r"((r)[0]), "=r"((r)[1]), "=r"((r)[2]), "=r"((r)[3]) : "r"(addr))

#define MMA(acc, a, b) \
    asm volatile("mma.sync.aligned.m16n8k16.row.col.f32.bf16.bf16.f32 " \
        "{%0,%1,%2,%3}, {%4,%5,%6,%7}, {%8,%9}, {%0,%1,%2,%3};" \
        : "+f"((acc)[0]), "+f"((acc)[1]), "+f"((acc)[2]), "+f"((acc)[3]) \
        : "r"((a)[0]), "r"((a)[1]), "r"((a)[2]), "r"((a)[3]), "r"((b)[0]), "r"((b)[1]))

// ---------------- small routing kernels ----------------
__global__ void init_kernel() {
    int t = threadIdx.x;
    if (t < E) { g_cnt[t] = 0; g_cur[t] = 0; }
}

__global__ void gate_kernel(const float* __restrict__ x, const float* __restrict__ gw) {
    int warp = (blockIdx.x * blockDim.x + threadIdx.x) >> 5;
    int lane = threadIdx.x & 31;
    if (warp >= T) return;
    const float* xr = x + (size_t)warp * DIM;
    float acc[E];
#pragma unroll
    for (int e = 0; e < E; e++) acc[e] = 0.f;
    for (int d = lane; d < DIM; d += 32) {
        float xv = xr[d];
        const float* g = gw + d * E;
#pragma unroll
        for (int e = 0; e < E; e++) acc[e] += xv * g[e];
    }
#pragma unroll
    for (int e = 0; e < E; e++)
#pragma unroll
        for (int o = 16; o; o >>= 1) acc[e] += __shfl_xor_sync(0xffffffffu, acc[e], o);
    if (lane == 0) {
        int i1 = 0; float l1 = acc[0];
#pragma unroll
        for (int e = 1; e < E; e++) if (acc[e] > l1) { l1 = acc[e]; i1 = e; }
        int i2 = -1; float l2 = -INFINITY;
#pragma unroll
        for (int e = 0; e < E; e++) if (e != i1 && acc[e] > l2) { l2 = acc[e]; i2 = e; }
        float w1 = 1.f / (1.f + expf(l2 - l1));   // exact normalized top-2 softmax
        g_topi[2 * warp] = i1;  g_topi[2 * warp + 1] = i2;
        g_topw[2 * warp] = w1;  g_topw[2 * warp + 1] = 1.f - w1;
        atomicAdd(&g_cnt[i1], 1);
        atomicAdd(&g_cnt[i2], 1);
    }
}

__global__ void scan_kernel() {
    if (threadIdx.x == 0) {
        int acc = 0;
#pragma unroll
        for (int e = 0; e < E; e++) { g_off[e] = acc; acc += g_cnt[e]; }
        g_off[E] = acc;
    }
}

__global__ void scatter_kernel() {
    int t = blockIdx.x * blockDim.x + threadIdx.x;
    if (t >= T) return;
#pragma unroll
    for (int k = 0; k < 2; k++) {
        int e = g_topi[2 * t + k];
        int p = g_off[e] + atomicAdd(&g_cur[e], 1);
        g_slot_token[p] = t;
        g_slot_e[p]     = e;
        g_slot_w[p]     = g_topw[2 * t + k];
        g_tok_slot[2 * t + k] = p;
    }
}

// ---------------- conversions: fp32 -> bf16 hi/lo ----------------
__global__ void convert_x_kernel(const float* __restrict__ x) {
    int i = blockIdx.x * blockDim.x + threadIdx.x;
    float4 v = ((const float4*)x)[i];
    float va[4] = {v.x, v.y, v.z, v.w};
    __nv_bfloat16 h[4], l[4];
#pragma unroll
    for (int j = 0; j < 4; j++) {
        h[j] = __float2bfloat16(va[j]);
        l[j] = __float2bfloat16(va[j] - __bfloat162float(h[j]));
    }
    __nv_bfloat162* ph = (__nv_bfloat162*)g_xh;
    __nv_bfloat162* pl = (__nv_bfloat162*)g_xl;
    __nv_bfloat162 a, b;
    a.x = h[0]; a.y = h[1]; b.x = h[2]; b.y = h[3];
    ph[2 * i] = a; ph[2 * i + 1] = b;
    a.x = l[0]; a.y = l[1]; b.x = l[2]; b.y = l[3];
    pl[2 * i] = a; pl[2 * i + 1] = b;
}

template <int WSEL>   // 0 -> w1, 1 -> w2
__global__ void convert_w_kernel(const float* __restrict__ W) {
    __nv_bfloat16* __restrict__ Wh = (WSEL == 0) ? g_w1h : g_w2h;
    __nv_bfloat16* __restrict__ Wl = (WSEL == 0) ? g_w1l : g_w2l;
    size_t i = (size_t)blockIdx.x * blockDim.x + threadIdx.x;
    float4 v = ((const float4*)W)[i];
    float va[4] = {v.x, v.y, v.z, v.w};
    __nv_bfloat16 h[4], l[4];
#pragma unroll
    for (int j = 0; j < 4; j++) {
        h[j] = __float2bfloat16(va[j]);
        l[j] = __float2bfloat16(va[j] - __bfloat162float(h[j]));
    }
    __nv_bfloat162* ph = (__nv_bfloat162*)Wh;
    __nv_bfloat162* pl = (__nv_bfloat162*)Wl;
    __nv_bfloat162 a, b;
    a.x = h[0]; a.y = h[1]; b.x = h[2]; b.y = h[3];
    ph[2 * i] = a; ph[2 * i + 1] = b;
    a.x = l[0]; a.y = l[1]; b.x = l[2]; b.y = l[3];
    pl[2 * i] = a; pl[2 * i + 1] = b;
}

// ---------------- mma.sync grouped GEMM ----------------
// Block tile 128(M) x 256(N), K-stage 32, 8 warps (2x4), warp tile 64x64.
// bf16 hi/lo split: acc += Ah*Bh + Ah*Bl + Al*Bh  (fp32 accum)
// A smem: [128][32] bf16, row stride 80B (conflict-free ldmatrix)
// B smem: [32][256] bf16, row stride 528B (conflict-free ldmatrix.trans)
#define A_STRIDE 80
#define B_STRIDE 528
#define AH_OFF   0
#define AL_OFF   (128 * A_STRIDE)            // 10240
#define BH_OFF   (2 * 128 * A_STRIDE)        // 20480
#define BL_OFF   (BH_OFF + 32 * B_STRIDE)    // 37376
#define STAGE_SZ (BL_OFF + 32 * B_STRIDE - BH_OFF + BH_OFF)  // 54272
#define NSTAGE   4
#define MM_SMEM  (1024 + NSTAGE * 54272)     // 218112

template <int NT, int KD, int MODE>
__global__ void __launch_bounds__(256, 1) mma_gemm(const float* __restrict__ bias) {
    const int e    = blockIdx.z;
    const int base = g_off[e];
    const int cnt  = g_off[e + 1] - base;
    const int row0 = blockIdx.y * 128;
    if (row0 >= cnt) return;
    const int n0 = blockIdx.x * 256;

    extern __shared__ __align__(128) char smem[];
    const uint32_t sb = s2u(smem);
    int* rowidx = (int*)smem;
    const int tid = threadIdx.x, wid = tid >> 5, lane = tid & 31;

    const __nv_bfloat16* __restrict__ Ahi = (MODE == 0) ? g_xh  : g_hbh;
    const __nv_bfloat16* __restrict__ Alo = (MODE == 0) ? g_xl  : g_hbl;
    const __nv_bfloat16* __restrict__ bhp =
        ((MODE == 0) ? g_w1h : g_w2h) + (size_t)e * KD * NT + n0;
    const __nv_bfloat16* __restrict__ blp =
        ((MODE == 0) ? g_w1l : g_w2l) + (size_t)e * KD * NT + n0;
    float* __restrict__ out = (MODE == 0) ? g_h : g_y;

    if (tid < 128) {
        int r = row0 + tid; if (r > cnt - 1) r = cnt - 1;
        rowidx[tid] = (MODE == 0) ? g_slot_token[base + r] : (base + r);
    }
    __syncthreads();

    // per-thread cp.async coordinates
    const int ar = tid >> 2, ac = tid & 3;       // A: rows ar, ar+64; 16B chunk ac
    const int br = tid >> 3, bc = tid & 7;       // B: row br; 16B chunks bc+8i

    auto issue = [&](int c) {
        const int k0 = c * 32;
        const uint32_t s = sb + 1024 + (c % NSTAGE) * 54272;
#pragma unroll
        for (int i = 0; i < 2; i++) {
            int row = ar + i * 64;
            size_t go = (size_t)rowidx[row] * KD + k0 + ac * 8;
            uint32_t so = s + row * A_STRIDE + ac * 16;
            CP_ASYNC(so + AH_OFF, Ahi + go);
            CP_ASYNC(so + AL_OFF, Alo + go);
        }
#pragma unroll
        for (int i = 0; i < 4; i++) {
            int ch = bc + i * 8;
            size_t go = (size_t)(k0 + br) * NT + ch * 8;
            uint32_t so = s + br * B_STRIDE + ch * 16;
            CP_ASYNC(so + BH_OFF, bhp + go);
            CP_ASYNC(so + BL_OFF, blp + go);
        }
        CP_COMMIT();
    };

    float acc[4][8][4];
#pragma unroll
    for (int i = 0; i < 4; i++)
#pragma unroll
        for (int j = 0; j < 8; j++)
#pragma unroll
            for (int q = 0; q < 4; q++) acc[i][j][q] = 0.f;

    const int warp_m = wid >> 2, warp_n = wid & 3;
    const int mat = lane >> 3, rin = lane & 7;
    const uint32_t aOffBase = (uint32_t)((warp_m * 64 + rin + (mat & 1) * 8) * A_STRIDE
                                         + (mat >> 1) * 16);
    const uint32_t bOffBase = (uint32_t)(((mat & 1) * 8 + rin) * B_STRIDE
                                         + (warp_n * 64 + (mat >> 1) * 8) * 2);

    constexpr int NCH = KD / 32;
    issue(0);
    issue(1);
    issue(2);

    for (int c = 0; c < NCH; c++) {
        CP_WAIT2();
        __syncthreads();
        const uint32_t s = sb + 1024 + (c % NSTAGE) * 54272;
#pragma unroll
        for (int ks = 0; ks < 2; ks++) {
            uint32_t ah[4][4], al[4][4];
            uint32_t aAddr = s + aOffBase + ks * 32;
#pragma unroll
            for (int i = 0; i < 4; i++) LDSM4(ah[i], aAddr + i * 16 * A_STRIDE);
#pragma unroll
            for (int i = 0; i < 4; i++) LDSM4(al[i], aAddr + AL_OFF + i * 16 * A_STRIDE);
#pragma unroll
            for (int jh = 0; jh < 2; jh++) {
                uint32_t bh[4][2], bl[4][2];
                uint32_t bAddr = s + bOffBase + ks * 16 * B_STRIDE + jh * 64;
                LDSM4T(&bh[0][0], bAddr + BH_OFF);
                LDSM4T(&bh[2][0], bAddr + BH_OFF + 32);
                LDSM4T(&bl[0][0], bAddr + BL_OFF);
                LDSM4T(&bl[2][0], bAddr + BL_OFF + 32);
#pragma unroll
                for (int i = 0; i < 4; i++)
#pragma unroll
                    for (int j = 0; j < 4; j++) MMA(acc[i][jh * 4 + j], ah[i], bh[j]);
#pragma unroll
                for (int i = 0; i < 4; i++)
#pragma unroll
                    for (int j = 0; j < 4; j++) MMA(acc[i][jh * 4 + j], ah[i], bl[j]);
#pragma unroll
                for (int i = 0; i < 4; i++)
#pragma unroll
                    for (int j = 0; j < 4; j++) MMA(acc[i][jh * 4 + j], al[i], bh[j]);
            }
        }
        if (c + 3 < NCH) issue(c + 3);
        else CP_COMMIT();
    }

    // epilogue
    const float* bp = bias + (size_t)e * NT;
#pragma unroll
    for (int i = 0; i < 4; i++) {
        int r1 = row0 + warp_m * 64 + i * 16 + (lane >> 2);
        int r2 = r1 + 8;
        bool v1 = r1 < cnt, v2 = r2 < cnt;
        float w1g = 1.f, w2g = 1.f;
        if (MODE == 1) {
            if (v1) w1g = g_slot_w[base + r1];
            if (v2) w2g = g_slot_w[base + r2];
        }
#pragma unroll
        for (int j = 0; j < 8; j++) {
            int col = n0 + warp_n * 64 + j * 8 + (lane & 3) * 2;
            float b0 = bp[col], b1 = bp[col + 1];
            if (v1) {
                float2 o = make_float2((acc[i][j][0] + b0) * w1g,
                                       (acc[i][j][1] + b1) * w1g);
                *(float2*)(out + (size_t)(base + r1) * NT + col) = o;
            }
            if (v2) {
                float2 o = make_float2((acc[i][j][2] + b0) * w2g,
                                       (acc[i][j][3] + b1) * w2g);
                *(float2*)(out + (size_t)(base + r2) * NT + col) = o;
            }
        }
    }
}

// ---------------- block reduction helper ----------------
__device__ __forceinline__ float2 block_reduce2(float a, float b) {
#pragma unroll
    for (int o = 16; o; o >>= 1) {
        a += __shfl_xor_sync(0xffffffffu, a, o);
        b += __shfl_xor_sync(0xffffffffu, b, o);
    }
    __shared__ float2 sm[8];
    int w = threadIdx.x >> 5, l = threadIdx.x & 31;
    if (l == 0) sm[w] = make_float2(a, b);
    __syncthreads();
    if (w == 0) {
        float2 v = (l < 8) ? sm[l] : make_float2(0.f, 0.f);
#pragma unroll
        for (int o = 4; o; o >>= 1) {
            v.x += __shfl_xor_sync(0xffffffffu, v.x, o);
            v.y += __shfl_xor_sync(0xffffffffu, v.y, o);
        }
        if (l == 0) sm[0] = v;
    }
    __syncthreads();
    return sm[0];
}

// ---------------- LN1 + exact GELU, emit bf16 hi/lo ----------------
__global__ __launch_bounds__(256) void ln_gelu_kernel(
    const float* __restrict__ ln1_g, const float* __restrict__ ln1_b) {
    int s = blockIdx.x;
    int e = g_slot_e[s];
    const float* row = g_h + (size_t)s * HDIM;
    int t = threadIdx.x;

    float4 v0 = ((const float4*)row)[t];
    float4 v1 = ((const float4*)row)[t + 256];
    float sum = v0.x + v0.y + v0.z + v0.w + v1.x + v1.y + v1.z + v1.w;
    float sq  = v0.x * v0.x + v0.y * v0.y + v0.z * v0.z + v0.w * v0.w
              + v1.x * v1.x + v1.y * v1.y + v1.z * v1.z + v1.w * v1.w;
    float2 r = block_reduce2(sum, sq);
    float mean = r.x * (1.f / HDIM);
    float var  = r.y * (1.f / HDIM) - mean * mean;
    float rstd = rsqrtf(var + EPS);

    const float4 gg0 = ((const float4*)(ln1_g + (size_t)e * HDIM))[t];
    const float4 gg1 = ((const float4*)(ln1_g + (size_t)e * HDIM))[t + 256];
    const float4 bb0 = ((const float4*)(ln1_b + (size_t)e * HDIM))[t];
    const float4 bb1 = ((const float4*)(ln1_b + (size_t)e * HDIM))[t + 256];

    float va[8] = {v0.x, v0.y, v0.z, v0.w, v1.x, v1.y, v1.z, v1.w};
    float ga[8] = {gg0.x, gg0.y, gg0.z, gg0.w, gg1.x, gg1.y, gg1.z, gg1.w};
    float ba[8] = {bb0.x, bb0.y, bb0.z, bb0.w, bb1.x, bb1.y, bb1.z, bb1.w};
    __nv_bfloat16 hv[8], lv[8];
#pragma unroll
    for (int i = 0; i < 8; i++) {
        float u = (va[i] - mean) * rstd * ga[i] + ba[i];
        float g = 0.5f * u * (1.f + erff(u * 0.70710678118654752f));
        hv[i] = __float2bfloat16(g);
        lv[i] = __float2bfloat16(g - __bfloat162float(hv[i]));
    }
    __nv_bfloat162* ph = (__nv_bfloat162*)(g_hbh + (size_t)s * HDIM);
    __nv_bfloat162* pl = (__nv_bfloat162*)(g_hbl + (size_t)s * HDIM);
    __nv_bfloat162 p;
    p.x = hv[0]; p.y = hv[1]; ph[2 * t] = p;
    p.x = hv[2]; p.y = hv[3]; ph[2 * t + 1] = p;
    p.x = hv[4]; p.y = hv[5]; ph[512 + 2 * t] = p;
    p.x = hv[6]; p.y = hv[7]; ph[512 + 2 * t + 1] = p;
    p.x = lv[0]; p.y = lv[1]; pl[2 * t] = p;
    p.x = lv[2]; p.y = lv[3]; pl[2 * t + 1] = p;
    p.x = lv[4]; p.y = lv[5]; pl[512 + 2 * t] = p;
    p.x = lv[6]; p.y = lv[7]; pl[512 + 2 * t + 1] = p;
}

// ---------------- combine: out = LN(x + y0 + y1) ----------------
__global__ __launch_bounds__(256) void combine_kernel(
    const float* __restrict__ x, const float* __restrict__ ln_g,
    const float* __restrict__ ln_b, float* __restrict__ outp) {
    int tkn = blockIdx.x;
    int s0 = g_tok_slot[2 * tkn], s1 = g_tok_slot[2 * tkn + 1];
    int t = threadIdx.x;

    float4 xv = ((const float4*)(x + (size_t)tkn * DIM))[t];
    float4 y0 = ((const float4*)(g_y + (size_t)s0 * DIM))[t];
    float4 y1 = ((const float4*)(g_y + (size_t)s1 * DIM))[t];
    float4 v = make_float4(xv.x + y0.x + y1.x, xv.y + y0.y + y1.y,
                           xv.z + y0.z + y1.z, xv.w + y0.w + y1.w);
    float sum = v.x + v.y + v.z + v.w;
    float sq  = v.x * v.x + v.y * v.y + v.z * v.z + v.w * v.w;
    float2 r = block_reduce2(sum, sq);
    float mean = r.x * (1.f / DIM);
    float var  = r.y * (1.f / DIM) - mean * mean;
    float rstd = rsqrtf(var + EPS);

    float4 gg = ((const float4*)ln_g)[t];
    float4 bb = ((const float4*)ln_b)[t];
    float4 o = make_float4((v.x - mean) * rstd * gg.x + bb.x,
                           (v.y - mean) * rstd * gg.y + bb.y,
                           (v.z - mean) * rstd * gg.z + bb.z,
                           (v.w - mean) * rstd * gg.w + bb.w);
    ((float4*)(outp + (size_t)tkn * DIM))[t] = o;
}

// ---------------- launch ----------------
extern "C" void kernel_launch(void* const* d_in, const int* in_sizes, int n_in,
                              void* d_out, int out_size) {
    const float* x      = (const float*)d_in[0];
    const float* gate_w = (const float*)d_in[1];
    const float* w1     = (const float*)d_in[2];
    const float* b1     = (const float*)d_in[3];
    const float* ln1_g  = (const float*)d_in[4];
    const float* ln1_b  = (const float*)d_in[5];
    const float* w2     = (const float*)d_in[6];
    const float* b2     = (const float*)d_in[7];
    const float* ln_g   = (const float*)d_in[8];
    const float* ln_b   = (const float*)d_in[9];
    float* outp = (float*)d_out;

    cudaFuncSetAttribute(mma_gemm<HDIM, DIM, 0>,
                         cudaFuncAttributeMaxDynamicSharedMemorySize, MM_SMEM);
    cudaFuncSetAttribute(mma_gemm<DIM, HDIM, 1>,
                         cudaFuncAttributeMaxDynamicSharedMemorySize, MM_SMEM);

    init_kernel<<<1, 32>>>();
    gate_kernel<<<T / 8, 256>>>(x, gate_w);
    scan_kernel<<<1, 32>>>();
    scatter_kernel<<<T / 256, 256>>>();

    convert_x_kernel<<<(T * DIM / 4) / 256, 256>>>(x);
    convert_w_kernel<0><<<(int)(((size_t)E * DIM * HDIM / 4) / 256), 256>>>(w1);
    convert_w_kernel<1><<<(int)(((size_t)E * HDIM * DIM / 4) / 256), 256>>>(w2);

    // GEMM1: gathered x @ w1 + b1 -> g_h (fp32)
    mma_gemm<HDIM, DIM, 0><<<dim3(HDIM / 256, T / 128, E), 256, MM_SMEM>>>(b1);
    ln_gelu_kernel<<<NSLOT, 256>>>(ln1_g, ln1_b);
    // GEMM2: act @ w2 + b2, gate-scaled -> g_y
    mma_gemm<DIM, HDIM, 1><<<dim3(DIM / 256, T / 128, E), 256, MM_SMEM>>>(b2);
    combine_kernel<<<T, 256>>>(x, ln_g, ln_b, outp);
}

// round 6
// speedup vs baseline: 4.7452x; 1.8663x over previous
#include <cuda_runtime.h>
#include <cuda_fp16.h>
#include <math.h>
#include <stdint.h>

#define T      4096
#define DIM    1024
#define E      8
#define HDIM   2048
#define NSLOT  (T * 2)
#define EPS    1e-5f

// ---------------- device scratch (static, allocation-free) ----------------
__device__ float g_h[(size_t)NSLOT * HDIM];
__device__ float g_y[(size_t)NSLOT * DIM];
__device__ __half g_xf[(size_t)T * DIM];
__device__ __half g_act[(size_t)NSLOT * HDIM];
__device__ __half g_w1f[(size_t)E * DIM * HDIM];   // [E][K=1024][N=2048]
__device__ __half g_w2f[(size_t)E * HDIM * DIM];   // [E][K=2048][N=1024]
__device__ int   g_cnt[E];
__device__ int   g_cur[E];
__device__ int   g_off[E + 1];
__device__ int   g_topi[NSLOT];
__device__ float g_topw[NSLOT];
__device__ int   g_slot_token[NSLOT];
__device__ int   g_slot_e[NSLOT];
__device__ float g_slot_w[NSLOT];
__device__ int   g_tok_slot[NSLOT];

// ---------------- PTX helpers ----------------
__device__ __forceinline__ uint32_t s2u(const void* p) {
    uint32_t a;
    asm("{ .reg .u64 t; cvta.to.shared.u64 t, %1; cvt.u32.u64 %0, t; }" : "=r"(a) : "l"(p));
    return a;
}

#define CP_ASYNC(sa, ga) \
    asm volatile("cp.async.cg.shared.global [%0], [%1], 16;" :: "r"(sa), "l"(ga))
#define CP_COMMIT() asm volatile("cp.async.commit_group;" ::: "memory")
#define CP_WAIT4()  asm volatile("cp.async.wait_group 4;" ::: "memory")

#define LDSM4(r, addr) \
    asm volatile("ldmatrix.sync.aligned.m8n8.x4.shared.b16 {%0,%1,%2,%3}, [%4];" \
        : "=r"((r)[0]), "=r"((r)[1]), "=r"((r)[2]), "=r"((r)[3]) : "r"(addr))
#define LDSM4T(r, addr) \
    asm volatile("ldmatrix.sync.aligned.m8n8.x4.trans.shared.b16 {%0,%1,%2,%3}, [%4];" \
        : "=r"((r)[0]), "=r"((r)[1]), "=r"((r)[2]), "=r"((r)[3]) : "r"(addr))

#define MMA(acc, a, b) \
    asm volatile("mma.sync.aligned.m16n8k16.row.col.f32.f16.f16.f32 " \
        "{%0,%1,%2,%3}, {%4,%5,%6,%7}, {%8,%9}, {%0,%1,%2,%3};" \
        : "+f"((acc)[0]), "+f"((acc)[1]), "+f"((acc)[2]), "+f"((acc)[3]) \
        : "r"((a)[0]), "r"((a)[1]), "r"((a)[2]), "r"((a)[3]), "r"((b)[0]), "r"((b)[1]))

// ---------------- small routing kernels ----------------
__global__ void init_kernel() {
    int t = threadIdx.x;
    if (t < E) { g_cnt[t] = 0; g_cur[t] = 0; }
}

__global__ void gate_kernel(const float* __restrict__ x, const float* __restrict__ gw) {
    int warp = (blockIdx.x * blockDim.x + threadIdx.x) >> 5;
    int lane = threadIdx.x & 31;
    if (warp >= T) return;
    const float* xr = x + (size_t)warp * DIM;
    float acc[E];
#pragma unroll
    for (int e = 0; e < E; e++) acc[e] = 0.f;
    for (int d = lane; d < DIM; d += 32) {
        float xv = xr[d];
        const float* g = gw + d * E;
#pragma unroll
        for (int e = 0; e < E; e++) acc[e] += xv * g[e];
    }
#pragma unroll
    for (int e = 0; e < E; e++)
#pragma unroll
        for (int o = 16; o; o >>= 1) acc[e] += __shfl_xor_sync(0xffffffffu, acc[e], o);
    if (lane == 0) {
        int i1 = 0; float l1 = acc[0];
#pragma unroll
        for (int e = 1; e < E; e++) if (acc[e] > l1) { l1 = acc[e]; i1 = e; }
        int i2 = -1; float l2 = -INFINITY;
#pragma unroll
        for (int e = 0; e < E; e++) if (e != i1 && acc[e] > l2) { l2 = acc[e]; i2 = e; }
        float w1 = 1.f / (1.f + expf(l2 - l1));   // exact normalized top-2 softmax
        g_topi[2 * warp] = i1;  g_topi[2 * warp + 1] = i2;
        g_topw[2 * warp] = w1;  g_topw[2 * warp + 1] = 1.f - w1;
        atomicAdd(&g_cnt[i1], 1);
        atomicAdd(&g_cnt[i2], 1);
    }
}

__global__ void scan_kernel() {
    if (threadIdx.x == 0) {
        int acc = 0;
#pragma unroll
        for (int e = 0; e < E; e++) { g_off[e] = acc; acc += g_cnt[e]; }
        g_off[E] = acc;
    }
}

__global__ void scatter_kernel() {
    int t = blockIdx.x * blockDim.x + threadIdx.x;
    if (t >= T) return;
#pragma unroll
    for (int k = 0; k < 2; k++) {
        int e = g_topi[2 * t + k];
        int p = g_off[e] + atomicAdd(&g_cur[e], 1);
        g_slot_token[p] = t;
        g_slot_e[p]     = e;
        g_slot_w[p]     = g_topw[2 * t + k];
        g_tok_slot[2 * t + k] = p;
    }
}

// ---------------- conversions: fp32 -> fp16 ----------------
__global__ void convert_x_kernel(const float* __restrict__ x) {
    int i = blockIdx.x * blockDim.x + threadIdx.x;
    float4 v = ((const float4*)x)[i];
    __half2* p = (__half2*)g_xf;
    p[2 * i]     = __floats2half2_rn(v.x, v.y);
    p[2 * i + 1] = __floats2half2_rn(v.z, v.w);
}

template <int WSEL>   // 0 -> w1, 1 -> w2
__global__ void convert_w_kernel(const float* __restrict__ W) {
    __half* __restrict__ Wf = (WSEL == 0) ? g_w1f : g_w2f;
    size_t i = (size_t)blockIdx.x * blockDim.x + threadIdx.x;
    float4 v = ((const float4*)W)[i];
    __half2* p = (__half2*)Wf;
    p[2 * i]     = __floats2half2_rn(v.x, v.y);
    p[2 * i + 1] = __floats2half2_rn(v.z, v.w);
}

// ---------------- mma.sync grouped GEMM (fp16, single term) ----------------
// Block tile 128(M) x 256(N), K-stage 32, 8 warps (2x4), warp tile 64x64.
// A smem: [128][32] fp16, row stride 80B (conflict-free ldmatrix)
// B smem: [32][256] fp16, row stride 528B (conflict-free ldmatrix.trans)
#define A_STRIDE 80
#define B_STRIDE 528
#define B_OFF    (128 * A_STRIDE)            // 10240
#define STAGE_SZ (B_OFF + 32 * B_STRIDE)     // 27136
#define NSTAGE   6
#define MM_SMEM  (1024 + NSTAGE * STAGE_SZ)  // 163840

template <int NT, int KD, int MODE>
__global__ void __launch_bounds__(256, 1) mma_gemm(const float* __restrict__ bias) {
    const int e    = blockIdx.z;
    const int base = g_off[e];
    const int cnt  = g_off[e + 1] - base;
    const int row0 = blockIdx.y * 128;
    if (row0 >= cnt) return;
    const int n0 = blockIdx.x * 256;

    extern __shared__ __align__(128) char smem[];
    const uint32_t sb = s2u(smem);
    int* rowidx = (int*)smem;
    const int tid = threadIdx.x, wid = tid >> 5, lane = tid & 31;

    const __half* __restrict__ Asrc = (MODE == 0) ? g_xf : g_act;
    const __half* __restrict__ Bsrc =
        ((MODE == 0) ? g_w1f : g_w2f) + (size_t)e * KD * NT + n0;
    float* __restrict__ out = (MODE == 0) ? g_h : g_y;

    if (tid < 128) {
        int r = row0 + tid; if (r > cnt - 1) r = cnt - 1;
        rowidx[tid] = (MODE == 0) ? g_slot_token[base + r] : (base + r);
    }
    __syncthreads();

    // per-thread cp.async coordinates
    const int ar = tid >> 2, ac = tid & 3;       // A: rows ar, ar+64; 16B chunk ac
    const int br = tid >> 3, bc = tid & 7;       // B: row br; 16B chunks bc+8i

    auto issue = [&](int c) {
        const int k0 = c * 32;
        const uint32_t s = sb + 1024 + (c % NSTAGE) * STAGE_SZ;
#pragma unroll
        for (int i = 0; i < 2; i++) {
            int row = ar + i * 64;
            size_t go = (size_t)rowidx[row] * KD + k0 + ac * 8;
            CP_ASYNC(s + row * A_STRIDE + ac * 16, Asrc + go);
        }
#pragma unroll
        for (int i = 0; i < 4; i++) {
            int ch = bc + i * 8;
            size_t go = (size_t)(k0 + br) * NT + ch * 8;
            CP_ASYNC(s + B_OFF + br * B_STRIDE + ch * 16, Bsrc + go);
        }
        CP_COMMIT();
    };

    float acc[4][8][4];
#pragma unroll
    for (int i = 0; i < 4; i++)
#pragma unroll
        for (int j = 0; j < 8; j++)
#pragma unroll
            for (int q = 0; q < 4; q++) acc[i][j][q] = 0.f;

    const int warp_m = wid >> 2, warp_n = wid & 3;
    const int mat = lane >> 3, rin = lane & 7;
    const uint32_t aOffBase = (uint32_t)((warp_m * 64 + rin + (mat & 1) * 8) * A_STRIDE
                                         + (mat >> 1) * 16);
    const uint32_t bOffBase = (uint32_t)(B_OFF + ((mat & 1) * 8 + rin) * B_STRIDE
                                         + (warp_n * 64 + (mat >> 1) * 8) * 2);

    constexpr int NCH = KD / 32;
    issue(0); issue(1); issue(2); issue(3); issue(4);

    for (int c = 0; c < NCH; c++) {
        CP_WAIT4();
        __syncthreads();
        const uint32_t s = sb + 1024 + (c % NSTAGE) * STAGE_SZ;
#pragma unroll
        for (int ks = 0; ks < 2; ks++) {
            uint32_t ah[4][4];
            uint32_t aAddr = s + aOffBase + ks * 32;
#pragma unroll
            for (int i = 0; i < 4; i++) LDSM4(ah[i], aAddr + i * 16 * A_STRIDE);
#pragma unroll
            for (int jh = 0; jh < 2; jh++) {
                uint32_t bh[4][2];
                uint32_t bAddr = s + bOffBase + ks * 16 * B_STRIDE + jh * 64;
                LDSM4T(&bh[0][0], bAddr);
                LDSM4T(&bh[2][0], bAddr + 32);
#pragma unroll
                for (int i = 0; i < 4; i++)
#pragma unroll
                    for (int j = 0; j < 4; j++) MMA(acc[i][jh * 4 + j], ah[i], bh[j]);
            }
        }
        if (c + 5 < NCH) issue(c + 5);
        else CP_COMMIT();
    }

    // epilogue
    const float* bp = bias + (size_t)e * NT;
#pragma unroll
    for (int i = 0; i < 4; i++) {
        int r1 = row0 + warp_m * 64 + i * 16 + (lane >> 2);
        int r2 = r1 + 8;
        bool v1 = r1 < cnt, v2 = r2 < cnt;
        float w1g = 1.f, w2g = 1.f;
        if (MODE == 1) {
            if (v1) w1g = g_slot_w[base + r1];
            if (v2) w2g = g_slot_w[base + r2];
        }
#pragma unroll
        for (int j = 0; j < 8; j++) {
            int col = n0 + warp_n * 64 + j * 8 + (lane & 3) * 2;
            float b0 = bp[col], b1 = bp[col + 1];
            if (v1) {
                float2 o = make_float2((acc[i][j][0] + b0) * w1g,
                                       (acc[i][j][1] + b1) * w1g);
                *(float2*)(out + (size_t)(base + r1) * NT + col) = o;
            }
            if (v2) {
                float2 o = make_float2((acc[i][j][2] + b0) * w2g,
                                       (acc[i][j][3] + b1) * w2g);
                *(float2*)(out + (size_t)(base + r2) * NT + col) = o;
            }
        }
    }
}

// ---------------- block reduction helper ----------------
__device__ __forceinline__ float2 block_reduce2(float a, float b) {
#pragma unroll
    for (int o = 16; o; o >>= 1) {
        a += __shfl_xor_sync(0xffffffffu, a, o);
        b += __shfl_xor_sync(0xffffffffu, b, o);
    }
    __shared__ float2 sm[8];
    int w = threadIdx.x >> 5, l = threadIdx.x & 31;
    if (l == 0) sm[w] = make_float2(a, b);
    __syncthreads();
    if (w == 0) {
        float2 v = (l < 8) ? sm[l] : make_float2(0.f, 0.f);
#pragma unroll
        for (int o = 4; o; o >>= 1) {
            v.x += __shfl_xor_sync(0xffffffffu, v.x, o);
            v.y += __shfl_xor_sync(0xffffffffu, v.y, o);
        }
        if (l == 0) sm[0] = v;
    }
    __syncthreads();
    return sm[0];
}

// ---------------- LN1 + exact GELU, emit fp16 ----------------
__global__ __launch_bounds__(256) void ln_gelu_kernel(
    const float* __restrict__ ln1_g, const float* __restrict__ ln1_b) {
    int s = blockIdx.x;
    int e = g_slot_e[s];
    const float* row = g_h + (size_t)s * HDIM;
    int t = threadIdx.x;

    float4 v0 = ((const float4*)row)[t];
    float4 v1 = ((const float4*)row)[t + 256];
    float sum = v0.x + v0.y + v0.z + v0.w + v1.x + v1.y + v1.z + v1.w;
    float sq  = v0.x * v0.x + v0.y * v0.y + v0.z * v0.z + v0.w * v0.w
              + v1.x * v1.x + v1.y * v1.y + v1.z * v1.z + v1.w * v1.w;
    float2 r = block_reduce2(sum, sq);
    float mean = r.x * (1.f / HDIM);
    float var  = r.y * (1.f / HDIM) - mean * mean;
    float rstd = rsqrtf(var + EPS);

    const float4 gg0 = ((const float4*)(ln1_g + (size_t)e * HDIM))[t];
    const float4 gg1 = ((const float4*)(ln1_g + (size_t)e * HDIM))[t + 256];
    const float4 bb0 = ((const float4*)(ln1_b + (size_t)e * HDIM))[t];
    const float4 bb1 = ((const float4*)(ln1_b + (size_t)e * HDIM))[t + 256];

    float va[8] = {v0.x, v0.y, v0.z, v0.w, v1.x, v1.y, v1.z, v1.w};
    float ga[8] = {gg0.x, gg0.y, gg0.z, gg0.w, gg1.x, gg1.y, gg1.z, gg1.w};
    float ba[8] = {bb0.x, bb0.y, bb0.z, bb0.w, bb1.x, bb1.y, bb1.z, bb1.w};
    float gv[8];
#pragma unroll
    for (int i = 0; i < 8; i++) {
        float u = (va[i] - mean) * rstd * ga[i] + ba[i];
        gv[i] = 0.5f * u * (1.f + erff(u * 0.70710678118654752f));
    }
    __half2* p = (__half2*)(g_act + (size_t)s * HDIM);
    p[2 * t]           = __floats2half2_rn(gv[0], gv[1]);
    p[2 * t + 1]       = __floats2half2_rn(gv[2], gv[3]);
    p[512 + 2 * t]     = __floats2half2_rn(gv[4], gv[5]);
    p[512 + 2 * t + 1] = __floats2half2_rn(gv[6], gv[7]);
}

// ---------------- combine: out = LN(x + y0 + y1) ----------------
__global__ __launch_bounds__(256) void combine_kernel(
    const float* __restrict__ x, const float* __restrict__ ln_g,
    const float* __restrict__ ln_b, float* __restrict__ outp) {
    int tkn = blockIdx.x;
    int s0 = g_tok_slot[2 * tkn], s1 = g_tok_slot[2 * tkn + 1];
    int t = threadIdx.x;

    float4 xv = ((const float4*)(x + (size_t)tkn * DIM))[t];
    float4 y0 = ((const float4*)(g_y + (size_t)s0 * DIM))[t];
    float4 y1 = ((const float4*)(g_y + (size_t)s1 * DIM))[t];
    float4 v = make_float4(xv.x + y0.x + y1.x, xv.y + y0.y + y1.y,
                           xv.z + y0.z + y1.z, xv.w + y0.w + y1.w);
    float sum = v.x + v.y + v.z + v.w;
    float sq  = v.x * v.x + v.y * v.y + v.z * v.z + v.w * v.w;
    float2 r = block_reduce2(sum, sq);
    float mean = r.x * (1.f / DIM);
    float var  = r.y * (1.f / DIM) - mean * mean;
    float rstd = rsqrtf(var + EPS);

    float4 gg = ((const float4*)ln_g)[t];
    float4 bb = ((const float4*)ln_b)[t];
    float4 o = make_float4((v.x - mean) * rstd * gg.x + bb.x,
                           (v.y - mean) * rstd * gg.y + bb.y,
                           (v.z - mean) * rstd * gg.z + bb.z,
                           (v.w - mean) * rstd * gg.w + bb.w);
    ((float4*)(outp + (size_t)tkn * DIM))[t] = o;
}

// ---------------- launch ----------------
extern "C" void kernel_launch(void* const* d_in, const int* in_sizes, int n_in,
                              void* d_out, int out_size) {
    const float* x      = (const float*)d_in[0];
    const float* gate_w = (const float*)d_in[1];
    const float* w1     = (const float*)d_in[2];
    const float* b1     = (const float*)d_in[3];
    const float* ln1_g  = (const float*)d_in[4];
    const float* ln1_b  = (const float*)d_in[5];
    const float* w2     = (const float*)d_in[6];
    const float* b2     = (const float*)d_in[7];
    const float* ln_g   = (const float*)d_in[8];
    const float* ln_b   = (const float*)d_in[9];
    float* outp = (float*)d_out;

    cudaFuncSetAttribute(mma_gemm<HDIM, DIM, 0>,
                         cudaFuncAttributeMaxDynamicSharedMemorySize, MM_SMEM);
    cudaFuncSetAttribute(mma_gemm<DIM, HDIM, 1>,
                         cudaFuncAttributeMaxDynamicSharedMemorySize, MM_SMEM);

    init_kernel<<<1, 32>>>();
    gate_kernel<<<T / 8, 256>>>(x, gate_w);
    scan_kernel<<<1, 32>>>();
    scatter_kernel<<<T / 256, 256>>>();

    convert_x_kernel<<<(T * DIM / 4) / 256, 256>>>(x);
    convert_w_kernel<0><<<(int)(((size_t)E * DIM * HDIM / 4) / 256), 256>>>(w1);
    convert_w_kernel<1><<<(int)(((size_t)E * HDIM * DIM / 4) / 256), 256>>>(w2);

    // GEMM1: gathered x @ w1 + b1 -> g_h (fp32)
    mma_gemm<HDIM, DIM, 0><<<dim3(HDIM / 256, T / 128, E), 256, MM_SMEM>>>(b1);
    ln_gelu_kernel<<<NSLOT, 256>>>(ln1_g, ln1_b);
    // GEMM2: act @ w2 + b2, gate-scaled -> g_y
    mma_gemm<DIM, HDIM, 1><<<dim3(DIM / 256, T / 128, E), 256, MM_SMEM>>>(b2);
    combine_kernel<<<T, 256>>>(x, ln_g, ln_b, outp);
}